// round 15
// baseline (speedup 1.0000x reference)
#include <cuda_runtime.h>
#include <cuda_fp16.h>
#include <cstdint>

#define NN 100000
#define EE 1600000
#define DD 128
#define NPAD 100096          // 1564 * 64
#define NGBLK 1564           // GEMM row blocks of 64
#define SCAN_B 1024
#define SCAN_NBLK 98
#define S_H 72               // smem row stride in halfs (64 data + 8 pad); conflict-free
#define A_TILE_H (64 * S_H)  // halfs per (64 x 64) A slab
#define B_TILE_H (128 * S_H) // halfs per (128 x 64) B slab
#define SMEM_DYN ((2 * A_TILE_H + 2 * B_TILE_H) * 2)  // 55296 bytes

// ------------------- device scratch (zero-initialized) -------------------
__device__ __half g_zh [(size_t)NPAD * DD];
__device__ __half g_xh [(size_t)NPAD * DD];
__device__ __half g_hh [(size_t)NPAD * DD];
__device__ __half g_mh [(size_t)NPAD * DD];
__device__ __half g_rhh[(size_t)NPAD * DD];
__device__ __half g_Wh [DD * DD];      // [n][k] = W[k][n]
__device__ __half g_Wch[DD * DD];
__device__ __half g_ugh[DD * 2 * DD];  // [n][k] direct
__device__ __half g_rgh[DD * 2 * DD];
__device__ int   g_deg[NN];
__device__ int   g_rowptr[NN + 1];
__device__ int   g_cursor[NN];
__device__ int   g_cols[EE];
__device__ float g_wsorted[EE];
__device__ int   g_bsums[SCAN_NBLK];

__device__ __forceinline__ float sigmoidf_(float x) { return 1.0f / (1.0f + __expf(-x)); }

__device__ __forceinline__ void mma16(float* d, const uint32_t* a, const uint32_t* b) {
    asm volatile(
        "mma.sync.aligned.m16n8k16.row.col.f32.f16.f16.f32 "
        "{%0,%1,%2,%3}, {%4,%5,%6,%7}, {%8,%9}, {%0,%1,%2,%3};"
        : "+f"(d[0]), "+f"(d[1]), "+f"(d[2]), "+f"(d[3])
        : "r"(a[0]), "r"(a[1]), "r"(a[2]), "r"(a[3]), "r"(b[0]), "r"(b[1]));
}
__device__ __forceinline__ uint32_t cvs(const void* p) {
    return (uint32_t)__cvta_generic_to_shared(p);
}
__device__ __forceinline__ void cpa16(uint32_t d, const void* s) {
    asm volatile("cp.async.cg.shared.global [%0], [%1], 16;" :: "r"(d), "l"(s) : "memory");
}
#define CP_COMMIT() asm volatile("cp.async.commit_group;" ::: "memory")
#define CP_WAIT(n)  asm volatile("cp.async.wait_group %0;" :: "n"(n) : "memory")

// ------------------- prep -------------------
__global__ void k_prepW(const float* __restrict__ W, const float* __restrict__ Wc) {
    int i = blockIdx.x * blockDim.x + threadIdx.x;
    if (i >= DD * DD) return;
    int n = i >> 7, k = i & 127;
    g_Wh[i]  = __float2half(W[k * DD + n]);
    g_Wch[i] = __float2half(Wc[k * DD + n]);
}
__global__ void k_prepG(const float* __restrict__ ugW, const float* __restrict__ rgW) {
    int i = blockIdx.x * blockDim.x + threadIdx.x;
    if (i >= DD * 2 * DD) return;
    g_ugh[i] = __float2half(ugW[i]);
    g_rgh[i] = __float2half(rgW[i]);
}
__global__ void k_prepX(const float* __restrict__ X) {
    int idx = blockIdx.x * blockDim.x + threadIdx.x;   // NPAD*32
    if (idx >= NPAD * 32) return;
    int row = idx >> 5;
    float4 v = make_float4(0.f, 0.f, 0.f, 0.f);
    if (row < NN) v = *(const float4*)&X[(size_t)idx * 4];
    __half2 p0 = __floats2half2_rn(v.x, v.y);
    __half2 p1 = __floats2half2_rn(v.z, v.w);
    uint2 w = make_uint2(*(uint32_t*)&p0, *(uint32_t*)&p1);
    *(uint2*)&g_xh[(size_t)idx * 4] = w;
}

// ------------------- CSR build -------------------
__global__ void k_zero_deg() {
    int i = blockIdx.x * blockDim.x + threadIdx.x;
    if (i < NN) g_deg[i] = 0;
}
__global__ void k_hist(const int* __restrict__ erow) {
    int e = blockIdx.x * blockDim.x + threadIdx.x;
    if (e < EE) atomicAdd(&g_deg[erow[e]], 1);
}
__global__ void k_scan1() {
    __shared__ int s[SCAN_B];
    int t = threadIdx.x;
    int i = blockIdx.x * SCAN_B + t;
    int v = (i < NN) ? g_deg[i] : 0;
    s[t] = v;
    __syncthreads();
    for (int off = 1; off < SCAN_B; off <<= 1) {
        int u = (t >= off) ? s[t - off] : 0;
        __syncthreads();
        s[t] += u;
        __syncthreads();
    }
    if (i < NN) g_rowptr[i] = s[t] - v;
    if (t == SCAN_B - 1) g_bsums[blockIdx.x] = s[t];
}
__global__ void k_scan2() {
    int acc = 0;
    for (int b = 0; b < SCAN_NBLK; b++) { int v = g_bsums[b]; g_bsums[b] = acc; acc += v; }
}
__global__ void k_scan3() {
    int i = blockIdx.x * blockDim.x + threadIdx.x;
    if (i < NN) {
        int v = g_rowptr[i] + g_bsums[i / SCAN_B];
        g_rowptr[i] = v;
        g_cursor[i] = v;
    }
    if (i == 0) g_rowptr[NN] = EE;
}
__global__ void k_fill(const int* __restrict__ erow, const int* __restrict__ ecol,
                       const float* __restrict__ ew) {
    int e = blockIdx.x * blockDim.x + threadIdx.x;
    if (e >= EE) return;
    int r = erow[e];
    int pos = atomicAdd(&g_cursor[r], 1);
    g_cols[pos]    = ecol[e];
    g_wsorted[pos] = ew[e];
}

// ------------------- fp16 GEMM core: 64x128 block, BK=64 slabs, 256 threads -------------------
// 8 warps: wm = w&1 (32-row half), wn = w>>1 (32-col group). Warp tile 32x32.
template <int KTOT, bool CONCAT>
__device__ __forceinline__ void gemm_h(
    const __half* __restrict__ A0, const __half* __restrict__ A1,
    const __half* __restrict__ B, int ldb,
    int rowbase, float acc[2][4][4])
{
    extern __shared__ __half smem[];
    constexpr int NIT = KTOT / 64;
    int t = threadIdx.x;
    int lane = t & 31, w = t >> 5;
    int wm = w & 1, wn = w >> 1;

#pragma unroll
    for (int mt = 0; mt < 2; mt++)
#pragma unroll
        for (int nt = 0; nt < 4; nt++)
#pragma unroll
            for (int r = 0; r < 4; r++) acc[mt][nt][r] = 0.0f;

    auto fill = [&](int it, int b) {
        int kb = it * 64;
        const __half* As = (CONCAT && kb >= 128) ? A1 : A0;
        int akb = (CONCAT && kb >= 128) ? kb - 128 : kb;
        __half* dA = smem + b * A_TILE_H;
        __half* dB = smem + 2 * A_TILE_H + b * B_TILE_H;
#pragma unroll
        for (int i = 0; i < 2; i++) {
            int idx = t + 256 * i;               // 512 = 64 rows x 8 chunks
            int row = idx >> 3, k8 = (idx & 7) * 8;
            cpa16(cvs(dA + row * S_H + k8), As + (size_t)(rowbase + row) * DD + akb + k8);
        }
#pragma unroll
        for (int i = 0; i < 4; i++) {
            int idx = t + 256 * i;               // 1024 = 128 rows x 8 chunks
            int n = idx >> 3, k8 = (idx & 7) * 8;
            cpa16(cvs(dB + n * S_H + k8), B + (size_t)n * ldb + kb + k8);
        }
        CP_COMMIT();
    };

    fill(0, 0);
#pragma unroll
    for (int it = 0; it < NIT; it++) {
        if (it + 1 < NIT) { fill(it + 1, (it + 1) & 1); CP_WAIT(1); }
        else              { CP_WAIT(0); }
        __syncthreads();
        const __half* sA = smem + (it & 1) * A_TILE_H;
        const __half* sB = smem + 2 * A_TILE_H + (it & 1) * B_TILE_H;
#pragma unroll
        for (int ks = 0; ks < 4; ks++) {
            int k0 = ks * 16;
            uint32_t af[2][4], bf[4][2];
#pragma unroll
            for (int mt = 0; mt < 2; mt++) {
                int m0 = wm * 32 + mt * 16;
                uint32_t a = cvs(sA + (m0 + (lane & 15)) * S_H + k0 + 8 * (lane >> 4));
                asm volatile("ldmatrix.sync.aligned.m8n8.x4.shared.b16 {%0,%1,%2,%3}, [%4];"
                             : "=r"(af[mt][0]), "=r"(af[mt][1]), "=r"(af[mt][2]), "=r"(af[mt][3])
                             : "r"(a));
            }
#pragma unroll
            for (int nt = 0; nt < 4; nt++) {
                int n0 = wn * 32 + nt * 8;
                uint32_t a = cvs(sB + (n0 + (lane & 7)) * S_H + k0 + 8 * ((lane >> 3) & 1));
                asm volatile("ldmatrix.sync.aligned.m8n8.x2.shared.b16 {%0,%1}, [%2];"
                             : "=r"(bf[nt][0]), "=r"(bf[nt][1]) : "r"(a));
            }
#pragma unroll
            for (int mt = 0; mt < 2; mt++)
#pragma unroll
                for (int nt = 0; nt < 4; nt++)
                    mma16(acc[mt][nt], af[mt], bf[nt]);
        }
        __syncthreads();
    }
}

// ------------------- init GEMM: h = X @ W + b (fp16 h only) -------------------
__global__ __launch_bounds__(256, 3) void k_gemm_init(const float* __restrict__ bias)
{
    float acc[2][4][4];
    int rowbase = blockIdx.x * 64;
    gemm_h<128, false>(g_xh, nullptr, g_Wh, DD, rowbase, acc);

    int t = threadIdx.x, lane = t & 31, w = t >> 5;
    int wm = w & 1, wn = w >> 1, g = lane >> 2, q = lane & 3;
#pragma unroll
    for (int mt = 0; mt < 2; mt++)
#pragma unroll
        for (int nt = 0; nt < 4; nt++) {
            int col = wn * 32 + nt * 8 + 2 * q;
            int row0 = rowbase + wm * 32 + mt * 16 + g;
            float b0 = bias[col], b1 = bias[col + 1];
#pragma unroll
            for (int hf = 0; hf < 2; hf++) {
                int row = row0 + hf * 8;
                size_t base = (size_t)row * DD + col;
                __half2 oh = __floats2half2_rn(acc[mt][nt][hf * 2] + b0,
                                               acc[mt][nt][hf * 2 + 1] + b1);
                *(uint32_t*)&g_hh[base] = *(uint32_t*)&oh;
            }
        }
}

// ------------------- SpMM (half gather, fp32 accum, half out, MLP=4) -------------------
__global__ void k_spmm() {
    int gwarp = (blockIdx.x * blockDim.x + threadIdx.x) >> 5;
    int lane = threadIdx.x & 31;
    if (gwarp >= NN) return;
    int s = g_rowptr[gwarp], e = g_rowptr[gwarp + 1];
    float4 acc = make_float4(0.f, 0.f, 0.f, 0.f);
    int i = s;
    for (; i + 4 <= e; i += 4) {
        int c0 = g_cols[i], c1 = g_cols[i + 1], c2 = g_cols[i + 2], c3 = g_cols[i + 3];
        float w0 = g_wsorted[i],     w1 = g_wsorted[i + 1];
        float w2 = g_wsorted[i + 2], w3 = g_wsorted[i + 3];
        uint2 r0 = *(const uint2*)&g_hh[(size_t)c0 * DD + lane * 4];
        uint2 r1 = *(const uint2*)&g_hh[(size_t)c1 * DD + lane * 4];
        uint2 r2 = *(const uint2*)&g_hh[(size_t)c2 * DD + lane * 4];
        uint2 r3 = *(const uint2*)&g_hh[(size_t)c3 * DD + lane * 4];
        float2 a0 = __half22float2(*(__half2*)&r0.x), a1 = __half22float2(*(__half2*)&r0.y);
        float2 b0 = __half22float2(*(__half2*)&r1.x), b1 = __half22float2(*(__half2*)&r1.y);
        float2 d0 = __half22float2(*(__half2*)&r2.x), d1 = __half22float2(*(__half2*)&r2.y);
        float2 e0 = __half22float2(*(__half2*)&r3.x), e1 = __half22float2(*(__half2*)&r3.y);
        acc.x += w0 * a0.x + w1 * b0.x + w2 * d0.x + w3 * e0.x;
        acc.y += w0 * a0.y + w1 * b0.y + w2 * d0.y + w3 * e0.y;
        acc.z += w0 * a1.x + w1 * b1.x + w2 * d1.x + w3 * e1.x;
        acc.w += w0 * a1.y + w1 * b1.y + w2 * d1.y + w3 * e1.y;
    }
    for (; i < e; i++) {
        int c = g_cols[i];
        float w0 = g_wsorted[i];
        uint2 r0 = *(const uint2*)&g_hh[(size_t)c * DD + lane * 4];
        float2 a0 = __half22float2(*(__half2*)&r0.x), a1 = __half22float2(*(__half2*)&r0.y);
        acc.x += w0 * a0.x; acc.y += w0 * a0.y; acc.z += w0 * a1.x; acc.w += w0 * a1.y;
    }
    __half2 p0 = __floats2half2_rn(acc.x, acc.y);
    __half2 p1 = __floats2half2_rn(acc.z, acc.w);
    uint2 o = make_uint2(*(uint32_t*)&p0, *(uint32_t*)&p1);
    *(uint2*)&g_mh[(size_t)gwarp * DD + lane * 4] = o;
}

// ------------------- gates GEMM: y=0 -> z=sig(.) fp16; y=1 -> rh=sig(.)*h fp16 -------------------
__global__ __launch_bounds__(256, 3) void k_gates1(
    const float* __restrict__ ugb, const float* __restrict__ rgb)
{
    float acc[2][4][4];
    int rowbase = blockIdx.x * 64;
    const __half* B = (blockIdx.y == 0) ? g_ugh : g_rgh;
    gemm_h<256, true>(g_hh, g_mh, B, 256, rowbase, acc);

    int t = threadIdx.x, lane = t & 31, w = t >> 5;
    int wm = w & 1, wn = w >> 1, g = lane >> 2, q = lane & 3;
#pragma unroll
    for (int mt = 0; mt < 2; mt++)
#pragma unroll
        for (int nt = 0; nt < 4; nt++) {
            int col = wn * 32 + nt * 8 + 2 * q;
            int row0 = rowbase + wm * 32 + mt * 16 + g;
            if (blockIdx.y == 0) {
                float b0 = ugb[col], b1 = ugb[col + 1];
#pragma unroll
                for (int hf = 0; hf < 2; hf++) {
                    int row = row0 + hf * 8;
                    __half2 oh = __floats2half2_rn(
                        sigmoidf_(acc[mt][nt][hf * 2] + b0),
                        sigmoidf_(acc[mt][nt][hf * 2 + 1] + b1));
                    *(uint32_t*)&g_zh[(size_t)row * DD + col] = *(uint32_t*)&oh;
                }
            } else {
                float b0 = rgb[col], b1 = rgb[col + 1];
#pragma unroll
                for (int hf = 0; hf < 2; hf++) {
                    int row = row0 + hf * 8;
                    size_t base = (size_t)row * DD + col;
                    uint32_t hr = *(const uint32_t*)&g_hh[base];
                    float2 h = __half22float2(*(__half2*)&hr);
                    __half2 oh = __floats2half2_rn(
                        sigmoidf_(acc[mt][nt][hf * 2] + b0) * h.x,
                        sigmoidf_(acc[mt][nt][hf * 2 + 1] + b1) * h.y);
                    *(uint32_t*)&g_rhh[base] = *(uint32_t*)&oh;
                }
            }
        }
}

// ------------------- candidate GEMM + update: h' = z*h + (1-z)*tanh(rh@Wc) -------------------
__global__ __launch_bounds__(256, 3) void k_gates2(float* __restrict__ out)
{
    float acc[2][4][4];
    int rowbase = blockIdx.x * 64;
    gemm_h<128, false>(g_rhh, nullptr, g_Wch, DD, rowbase, acc);

    int t = threadIdx.x, lane = t & 31, w = t >> 5;
    int wm = w & 1, wn = w >> 1, g = lane >> 2, q = lane & 3;
#pragma unroll
    for (int mt = 0; mt < 2; mt++)
#pragma unroll
        for (int nt = 0; nt < 4; nt++) {
            int col = wn * 32 + nt * 8 + 2 * q;
            int row0 = rowbase + wm * 32 + mt * 16 + g;
#pragma unroll
            for (int hf = 0; hf < 2; hf++) {
                int row = row0 + hf * 8;
                size_t base = (size_t)row * DD + col;
                uint32_t zr = *(const uint32_t*)&g_zh[base];
                float2 zz = __half22float2(*(__half2*)&zr);
                uint32_t hr = *(const uint32_t*)&g_hh[base];
                float2 hh = __half22float2(*(__half2*)&hr);
                float c0 = tanhf(acc[mt][nt][hf * 2]);
                float c1 = tanhf(acc[mt][nt][hf * 2 + 1]);
                float2 o = make_float2(zz.x * hh.x + (1.f - zz.x) * c0,
                                       zz.y * hh.y + (1.f - zz.y) * c1);
                if (out != nullptr) {
                    if (row < NN) *(float2*)&out[base] = o;
                } else {
                    __half2 oh = __floats2half2_rn(o.x, o.y);
                    *(uint32_t*)&g_hh[base] = *(uint32_t*)&oh;
                }
            }
        }
}

// ------------------- launch -------------------
extern "C" void kernel_launch(void* const* d_in, const int* in_sizes, int n_in,
                              void* d_out, int out_size) {
    const float* input = (const float*)d_in[0];
    const int*   erow  = (const int*)d_in[1];
    const int*   ecol  = (const int*)d_in[2];
    const float* ew    = (const float*)d_in[3];
    const float* W     = (const float*)d_in[4];
    const float* bias  = (const float*)d_in[5];
    const float* Wc    = (const float*)d_in[6];
    const float* ugW   = (const float*)d_in[7];
    const float* ugb   = (const float*)d_in[8];
    const float* rgW   = (const float*)d_in[9];
    const float* rgb   = (const float*)d_in[10];
    float* out = (float*)d_out;

    static int smem_set = 0;
    if (!smem_set) {
        cudaFuncSetAttribute(k_gemm_init, cudaFuncAttributeMaxDynamicSharedMemorySize, SMEM_DYN);
        cudaFuncSetAttribute(k_gates1,    cudaFuncAttributeMaxDynamicSharedMemorySize, SMEM_DYN);
        cudaFuncSetAttribute(k_gates2,    cudaFuncAttributeMaxDynamicSharedMemorySize, SMEM_DYN);
        smem_set = 1;
    }

    k_prepW<<<(DD * DD + 255) / 256, 256>>>(W, Wc);                 // 0
    k_prepX<<<(NPAD * 32 + 255) / 256, 256>>>(input);               // 1
    k_prepG<<<(DD * 2 * DD + 255) / 256, 256>>>(ugW, rgW);          // 2
    k_gemm_init<<<NGBLK, 256, SMEM_DYN>>>(bias);                    // 3 <- profiled
    k_zero_deg<<<(NN + 255) / 256, 256>>>();                        // 4
    k_hist<<<(EE + 255) / 256, 256>>>(erow);                        // 5
    k_scan1<<<SCAN_NBLK, SCAN_B>>>();
    k_scan2<<<1, 1>>>();
    k_scan3<<<(NN + 255) / 256, 256>>>();
    k_fill<<<(EE + 255) / 256, 256>>>(erow, ecol, ew);

    for (int s = 0; s < 3; s++) {
        k_spmm<<<(NN * 32 + 255) / 256, 256>>>();
        dim3 gg(NGBLK, 2);
        k_gates1<<<gg, 256, SMEM_DYN>>>(ugb, rgb);
        k_gates2<<<NGBLK, 256, SMEM_DYN>>>((s == 2) ? out : (float*)nullptr);
    }
}

// round 16
// speedup vs baseline: 1.4113x; 1.4113x over previous
#include <cuda_runtime.h>
#include <cuda_fp16.h>
#include <cstdint>

#define NN 100000
#define EE 1600000
#define DD 128
#define NPAD 100096          // 782 * 128
#define NGBLK 782
#define SCAN_B 1024
#define SCAN_NBLK 98
#define S_H 72               // smem row stride in halfs (64 data + 8 pad); conflict-free
#define TILE_H (128 * S_H)   // halfs per (128 x 64) tile buffer
#define SMEM_DYN (4 * TILE_H * 2)  // A0,A1,B0,B1 = 73728 bytes

// ------------------- device scratch (zero-initialized) -------------------
__device__ __half g_zh [(size_t)NPAD * DD];
__device__ __half g_xh [(size_t)NPAD * DD];
__device__ __half g_hh [(size_t)NPAD * DD];
__device__ __half g_mh [(size_t)NPAD * DD];
__device__ __half g_rhh[(size_t)NPAD * DD];
__device__ __half g_Wh [DD * DD];      // [n][k] = W[k][n]
__device__ __half g_Wch[DD * DD];
__device__ __half g_ugh[DD * 2 * DD];  // [n][k] direct
__device__ __half g_rgh[DD * 2 * DD];
__device__ int   g_deg[NN];
__device__ int   g_rowptr[NN + 1];
__device__ int   g_cursor[NN];
__device__ int   g_cols[EE];
__device__ float g_wsorted[EE];
__device__ int   g_bsums[SCAN_NBLK];

__device__ __forceinline__ float sigmoidf_(float x) { return 1.0f / (1.0f + __expf(-x)); }

__device__ __forceinline__ void mma16(float* d, const uint32_t* a, const uint32_t* b) {
    asm volatile(
        "mma.sync.aligned.m16n8k16.row.col.f32.f16.f16.f32 "
        "{%0,%1,%2,%3}, {%4,%5,%6,%7}, {%8,%9}, {%0,%1,%2,%3};"
        : "+f"(d[0]), "+f"(d[1]), "+f"(d[2]), "+f"(d[3])
        : "r"(a[0]), "r"(a[1]), "r"(a[2]), "r"(a[3]), "r"(b[0]), "r"(b[1]));
}
__device__ __forceinline__ uint32_t cvs(const void* p) {
    return (uint32_t)__cvta_generic_to_shared(p);
}
__device__ __forceinline__ void cpa16(uint32_t d, const void* s) {
    asm volatile("cp.async.cg.shared.global [%0], [%1], 16;" :: "r"(d), "l"(s) : "memory");
}
#define CP_COMMIT() asm volatile("cp.async.commit_group;" ::: "memory")
#define CP_WAIT(n)  asm volatile("cp.async.wait_group %0;" :: "n"(n) : "memory")

// ------------------- prep -------------------
__global__ void k_prepW(const float* __restrict__ W, const float* __restrict__ Wc) {
    int i = blockIdx.x * blockDim.x + threadIdx.x;
    if (i >= DD * DD) return;
    int n = i >> 7, k = i & 127;
    g_Wh[i]  = __float2half(W[k * DD + n]);
    g_Wch[i] = __float2half(Wc[k * DD + n]);
}
__global__ void k_prepG(const float* __restrict__ ugW, const float* __restrict__ rgW) {
    int i = blockIdx.x * blockDim.x + threadIdx.x;
    if (i >= DD * 2 * DD) return;
    g_ugh[i] = __float2half(ugW[i]);
    g_rgh[i] = __float2half(rgW[i]);
}
__global__ void k_prepX(const float* __restrict__ X) {
    int idx = blockIdx.x * blockDim.x + threadIdx.x;   // NPAD*32
    if (idx >= NPAD * 32) return;
    int row = idx >> 5;
    float4 v = make_float4(0.f, 0.f, 0.f, 0.f);
    if (row < NN) v = *(const float4*)&X[(size_t)idx * 4];
    __half2 p0 = __floats2half2_rn(v.x, v.y);
    __half2 p1 = __floats2half2_rn(v.z, v.w);
    uint2 w = make_uint2(*(uint32_t*)&p0, *(uint32_t*)&p1);
    *(uint2*)&g_xh[(size_t)idx * 4] = w;
}

// ------------------- CSR build -------------------
__global__ void k_zero_deg() {
    int i = blockIdx.x * blockDim.x + threadIdx.x;
    if (i < NN) g_deg[i] = 0;
}
__global__ void k_hist(const int* __restrict__ erow) {
    int e = blockIdx.x * blockDim.x + threadIdx.x;
    if (e < EE) atomicAdd(&g_deg[erow[e]], 1);
}
__global__ void k_scan1() {
    __shared__ int s[SCAN_B];
    int t = threadIdx.x;
    int i = blockIdx.x * SCAN_B + t;
    int v = (i < NN) ? g_deg[i] : 0;
    s[t] = v;
    __syncthreads();
    for (int off = 1; off < SCAN_B; off <<= 1) {
        int u = (t >= off) ? s[t - off] : 0;
        __syncthreads();
        s[t] += u;
        __syncthreads();
    }
    if (i < NN) g_rowptr[i] = s[t] - v;
    if (t == SCAN_B - 1) g_bsums[blockIdx.x] = s[t];
}
__global__ void k_scan2() {
    int acc = 0;
    for (int b = 0; b < SCAN_NBLK; b++) { int v = g_bsums[b]; g_bsums[b] = acc; acc += v; }
}
__global__ void k_scan3() {
    int i = blockIdx.x * blockDim.x + threadIdx.x;
    if (i < NN) {
        int v = g_rowptr[i] + g_bsums[i / SCAN_B];
        g_rowptr[i] = v;
        g_cursor[i] = v;
    }
    if (i == 0) g_rowptr[NN] = EE;
}
__global__ void k_fill(const int* __restrict__ erow, const int* __restrict__ ecol,
                       const float* __restrict__ ew) {
    int e = blockIdx.x * blockDim.x + threadIdx.x;
    if (e >= EE) return;
    int r = erow[e];
    int pos = atomicAdd(&g_cursor[r], 1);
    g_cols[pos]    = ecol[e];
    g_wsorted[pos] = ew[e];
}

// ------------------- fp16 GEMM core: 128x128 block, BK=64 slabs, 256 threads -------------------
template <int KTOT, bool CONCAT>
__device__ __forceinline__ void gemm_h(
    const __half* __restrict__ A0, const __half* __restrict__ A1,
    const __half* __restrict__ B, int ldb,
    int rowbase, float acc[4][4][4])
{
    extern __shared__ __half smem[];
    constexpr int NIT = KTOT / 64;
    int t = threadIdx.x;
    int lane = t & 31, w = t >> 5;
    int wm = w & 1, wn = w >> 1;

#pragma unroll
    for (int mt = 0; mt < 4; mt++)
#pragma unroll
        for (int nt = 0; nt < 4; nt++)
#pragma unroll
            for (int r = 0; r < 4; r++) acc[mt][nt][r] = 0.0f;

    auto fill = [&](int it, int b) {
        int kb = it * 64;
        const __half* As = (CONCAT && kb >= 128) ? A1 : A0;
        int akb = (CONCAT && kb >= 128) ? kb - 128 : kb;
        __half* dA = smem + b * TILE_H;
        __half* dB = smem + 2 * TILE_H + b * TILE_H;
#pragma unroll
        for (int i = 0; i < 4; i++) {
            int idx = t + 256 * i;
            int row = idx >> 3, k8 = (idx & 7) * 8;
            cpa16(cvs(dA + row * S_H + k8), As + (size_t)(rowbase + row) * DD + akb + k8);
        }
#pragma unroll
        for (int i = 0; i < 4; i++) {
            int idx = t + 256 * i;
            int n = idx >> 3, k8 = (idx & 7) * 8;
            cpa16(cvs(dB + n * S_H + k8), B + (size_t)n * ldb + kb + k8);
        }
        CP_COMMIT();
    };

    fill(0, 0);
#pragma unroll
    for (int it = 0; it < NIT; it++) {
        if (it + 1 < NIT) { fill(it + 1, (it + 1) & 1); CP_WAIT(1); }
        else              { CP_WAIT(0); }
        __syncthreads();
        const __half* sA = smem + (it & 1) * TILE_H;
        const __half* sB = smem + 2 * TILE_H + (it & 1) * TILE_H;
#pragma unroll
        for (int ks = 0; ks < 4; ks++) {
            int k0 = ks * 16;
            uint32_t af[4][4], bf[4][2];
#pragma unroll
            for (int mt = 0; mt < 4; mt++) {
                int m0 = wm * 64 + mt * 16;
                uint32_t a = cvs(sA + (m0 + (lane & 15)) * S_H + k0 + 8 * (lane >> 4));
                asm volatile("ldmatrix.sync.aligned.m8n8.x4.shared.b16 {%0,%1,%2,%3}, [%4];"
                             : "=r"(af[mt][0]), "=r"(af[mt][1]), "=r"(af[mt][2]), "=r"(af[mt][3])
                             : "r"(a));
            }
#pragma unroll
            for (int nt = 0; nt < 4; nt++) {
                int n0 = wn * 32 + nt * 8;
                uint32_t a = cvs(sB + (n0 + (lane & 7)) * S_H + k0 + 8 * ((lane >> 3) & 1));
                asm volatile("ldmatrix.sync.aligned.m8n8.x2.shared.b16 {%0,%1}, [%2];"
                             : "=r"(bf[nt][0]), "=r"(bf[nt][1]) : "r"(a));
            }
#pragma unroll
            for (int mt = 0; mt < 4; mt++)
#pragma unroll
                for (int nt = 0; nt < 4; nt++)
                    mma16(acc[mt][nt], af[mt], bf[nt]);
        }
        __syncthreads();
    }
}

// ------------------- init GEMM: h = X @ W + b (fp16 h only) -------------------
__global__ __launch_bounds__(256) void k_gemm_init(const float* __restrict__ bias)
{
    float acc[4][4][4];
    int rowbase = blockIdx.x * 128;
    gemm_h<128, false>(g_xh, nullptr, g_Wh, DD, rowbase, acc);

    int t = threadIdx.x, lane = t & 31, w = t >> 5;
    int wm = w & 1, wn = w >> 1, g = lane >> 2, q = lane & 3;
#pragma unroll
    for (int mt = 0; mt < 4; mt++)
#pragma unroll
        for (int nt = 0; nt < 4; nt++) {
            int col = wn * 32 + nt * 8 + 2 * q;
            int row0 = rowbase + wm * 64 + mt * 16 + g;
            float b0 = bias[col], b1 = bias[col + 1];
#pragma unroll
            for (int hf = 0; hf < 2; hf++) {
                int row = row0 + hf * 8;
                size_t base = (size_t)row * DD + col;
                __half2 oh = __floats2half2_rn(acc[mt][nt][hf * 2] + b0,
                                               acc[mt][nt][hf * 2 + 1] + b1);
                *(uint32_t*)&g_hh[base] = *(uint32_t*)&oh;
            }
        }
}

// ------------------- SpMM: 2 rows/warp, 16 lanes/row, uint4 gathers, MLP=4 -------------------
__global__ void k_spmm() {
    int warp = (blockIdx.x * blockDim.x + threadIdx.x) >> 5;
    int lane = threadIdx.x & 31;
    int row = warp * 2 + (lane >> 4);     // half-warp per row
    if (row >= NN) return;
    int hl = lane & 15;                   // lane within half-warp: 8 halfs each
    int s = g_rowptr[row], e = g_rowptr[row + 1];
    float4 acc0 = make_float4(0.f, 0.f, 0.f, 0.f);
    float4 acc1 = make_float4(0.f, 0.f, 0.f, 0.f);
    size_t coff = (size_t)hl * 8;
    int i = s;
    for (; i + 4 <= e; i += 4) {
        int c0 = g_cols[i], c1 = g_cols[i + 1], c2 = g_cols[i + 2], c3 = g_cols[i + 3];
        float w0 = g_wsorted[i],     w1 = g_wsorted[i + 1];
        float w2 = g_wsorted[i + 2], w3 = g_wsorted[i + 3];
        uint4 r0 = *(const uint4*)&g_hh[(size_t)c0 * DD + coff];
        uint4 r1 = *(const uint4*)&g_hh[(size_t)c1 * DD + coff];
        uint4 r2 = *(const uint4*)&g_hh[(size_t)c2 * DD + coff];
        uint4 r3 = *(const uint4*)&g_hh[(size_t)c3 * DD + coff];
        float2 v;
        v = __half22float2(*(__half2*)&r0.x); acc0.x += w0 * v.x; acc0.y += w0 * v.y;
        v = __half22float2(*(__half2*)&r0.y); acc0.z += w0 * v.x; acc0.w += w0 * v.y;
        v = __half22float2(*(__half2*)&r0.z); acc1.x += w0 * v.x; acc1.y += w0 * v.y;
        v = __half22float2(*(__half2*)&r0.w); acc1.z += w0 * v.x; acc1.w += w0 * v.y;
        v = __half22float2(*(__half2*)&r1.x); acc0.x += w1 * v.x; acc0.y += w1 * v.y;
        v = __half22float2(*(__half2*)&r1.y); acc0.z += w1 * v.x; acc0.w += w1 * v.y;
        v = __half22float2(*(__half2*)&r1.z); acc1.x += w1 * v.x; acc1.y += w1 * v.y;
        v = __half22float2(*(__half2*)&r1.w); acc1.z += w1 * v.x; acc1.w += w1 * v.y;
        v = __half22float2(*(__half2*)&r2.x); acc0.x += w2 * v.x; acc0.y += w2 * v.y;
        v = __half22float2(*(__half2*)&r2.y); acc0.z += w2 * v.x; acc0.w += w2 * v.y;
        v = __half22float2(*(__half2*)&r2.z); acc1.x += w2 * v.x; acc1.y += w2 * v.y;
        v = __half22float2(*(__half2*)&r2.w); acc1.z += w2 * v.x; acc1.w += w2 * v.y;
        v = __half22float2(*(__half2*)&r3.x); acc0.x += w3 * v.x; acc0.y += w3 * v.y;
        v = __half22float2(*(__half2*)&r3.y); acc0.z += w3 * v.x; acc0.w += w3 * v.y;
        v = __half22float2(*(__half2*)&r3.z); acc1.x += w3 * v.x; acc1.y += w3 * v.y;
        v = __half22float2(*(__half2*)&r3.w); acc1.z += w3 * v.x; acc1.w += w3 * v.y;
    }
    for (; i < e; i++) {
        int c = g_cols[i];
        float w0 = g_wsorted[i];
        uint4 r0 = *(const uint4*)&g_hh[(size_t)c * DD + coff];
        float2 v;
        v = __half22float2(*(__half2*)&r0.x); acc0.x += w0 * v.x; acc0.y += w0 * v.y;
        v = __half22float2(*(__half2*)&r0.y); acc0.z += w0 * v.x; acc0.w += w0 * v.y;
        v = __half22float2(*(__half2*)&r0.z); acc1.x += w0 * v.x; acc1.y += w0 * v.y;
        v = __half22float2(*(__half2*)&r0.w); acc1.z += w0 * v.x; acc1.w += w0 * v.y;
    }
    __half2 p0 = __floats2half2_rn(acc0.x, acc0.y);
    __half2 p1 = __floats2half2_rn(acc0.z, acc0.w);
    __half2 p2 = __floats2half2_rn(acc1.x, acc1.y);
    __half2 p3 = __floats2half2_rn(acc1.z, acc1.w);
    uint4 o = make_uint4(*(uint32_t*)&p0, *(uint32_t*)&p1, *(uint32_t*)&p2, *(uint32_t*)&p3);
    *(uint4*)&g_mh[(size_t)row * DD + coff] = o;
}

// ------------------- gates GEMM: y=0 -> z=sig(.) fp16; y=1 -> rh=sig(.)*h fp16 -------------------
__global__ __launch_bounds__(256) void k_gates1(
    const float* __restrict__ ugb, const float* __restrict__ rgb)
{
    float acc[4][4][4];
    int rowbase = blockIdx.x * 128;
    const __half* B = (blockIdx.y == 0) ? g_ugh : g_rgh;
    gemm_h<256, true>(g_hh, g_mh, B, 256, rowbase, acc);

    int t = threadIdx.x, lane = t & 31, w = t >> 5;
    int wm = w & 1, wn = w >> 1, g = lane >> 2, q = lane & 3;
#pragma unroll
    for (int mt = 0; mt < 4; mt++)
#pragma unroll
        for (int nt = 0; nt < 4; nt++) {
            int col = wn * 32 + nt * 8 + 2 * q;
            int row0 = rowbase + wm * 64 + mt * 16 + g;
            if (blockIdx.y == 0) {
                float b0 = ugb[col], b1 = ugb[col + 1];
#pragma unroll
                for (int hf = 0; hf < 2; hf++) {
                    int row = row0 + hf * 8;
                    __half2 oh = __floats2half2_rn(
                        sigmoidf_(acc[mt][nt][hf * 2] + b0),
                        sigmoidf_(acc[mt][nt][hf * 2 + 1] + b1));
                    *(uint32_t*)&g_zh[(size_t)row * DD + col] = *(uint32_t*)&oh;
                }
            } else {
                float b0 = rgb[col], b1 = rgb[col + 1];
#pragma unroll
                for (int hf = 0; hf < 2; hf++) {
                    int row = row0 + hf * 8;
                    size_t base = (size_t)row * DD + col;
                    uint32_t hr = *(const uint32_t*)&g_hh[base];
                    float2 h = __half22float2(*(__half2*)&hr);
                    __half2 oh = __floats2half2_rn(
                        sigmoidf_(acc[mt][nt][hf * 2] + b0) * h.x,
                        sigmoidf_(acc[mt][nt][hf * 2 + 1] + b1) * h.y);
                    *(uint32_t*)&g_rhh[base] = *(uint32_t*)&oh;
                }
            }
        }
}

// ------------------- candidate GEMM + update: h' = z*h + (1-z)*tanh(rh@Wc) -------------------
__global__ __launch_bounds__(256) void k_gates2(float* __restrict__ out)
{
    float acc[4][4][4];
    int rowbase = blockIdx.x * 128;
    gemm_h<128, false>(g_rhh, nullptr, g_Wch, DD, rowbase, acc);

    int t = threadIdx.x, lane = t & 31, w = t >> 5;
    int wm = w & 1, wn = w >> 1, g = lane >> 2, q = lane & 3;
#pragma unroll
    for (int mt = 0; mt < 4; mt++)
#pragma unroll
        for (int nt = 0; nt < 4; nt++) {
            int col = wn * 32 + nt * 8 + 2 * q;
            int row0 = rowbase + wm * 64 + mt * 16 + g;
#pragma unroll
            for (int hf = 0; hf < 2; hf++) {
                int row = row0 + hf * 8;
                size_t base = (size_t)row * DD + col;
                uint32_t zr = *(const uint32_t*)&g_zh[base];
                float2 zz = __half22float2(*(__half2*)&zr);
                uint32_t hr = *(const uint32_t*)&g_hh[base];
                float2 hh = __half22float2(*(__half2*)&hr);
                float c0 = tanhf(acc[mt][nt][hf * 2]);
                float c1 = tanhf(acc[mt][nt][hf * 2 + 1]);
                float2 o = make_float2(zz.x * hh.x + (1.f - zz.x) * c0,
                                       zz.y * hh.y + (1.f - zz.y) * c1);
                if (out != nullptr) {
                    if (row < NN) *(float2*)&out[base] = o;
                } else {
                    __half2 oh = __floats2half2_rn(o.x, o.y);
                    *(uint32_t*)&g_hh[base] = *(uint32_t*)&oh;
                }
            }
        }
}

// ------------------- launch -------------------
extern "C" void kernel_launch(void* const* d_in, const int* in_sizes, int n_in,
                              void* d_out, int out_size) {
    const float* input = (const float*)d_in[0];
    const int*   erow  = (const int*)d_in[1];
    const int*   ecol  = (const int*)d_in[2];
    const float* ew    = (const float*)d_in[3];
    const float* W     = (const float*)d_in[4];
    const float* bias  = (const float*)d_in[5];
    const float* Wc    = (const float*)d_in[6];
    const float* ugW   = (const float*)d_in[7];
    const float* ugb   = (const float*)d_in[8];
    const float* rgW   = (const float*)d_in[9];
    const float* rgb   = (const float*)d_in[10];
    float* out = (float*)d_out;

    static int smem_set = 0;
    if (!smem_set) {
        cudaFuncSetAttribute(k_gemm_init, cudaFuncAttributeMaxDynamicSharedMemorySize, SMEM_DYN);
        cudaFuncSetAttribute(k_gates1,    cudaFuncAttributeMaxDynamicSharedMemorySize, SMEM_DYN);
        cudaFuncSetAttribute(k_gates2,    cudaFuncAttributeMaxDynamicSharedMemorySize, SMEM_DYN);
        smem_set = 1;
    }

    k_prepW<<<(DD * DD + 255) / 256, 256>>>(W, Wc);                 // 0
    k_prepX<<<(NPAD * 32 + 255) / 256, 256>>>(input);               // 1
    k_prepG<<<(DD * 2 * DD + 255) / 256, 256>>>(ugW, rgW);          // 2
    k_gemm_init<<<NGBLK, 256, SMEM_DYN>>>(bias);                    // 3 <- profiled
    k_zero_deg<<<(NN + 255) / 256, 256>>>();                        // 4
    k_hist<<<(EE + 255) / 256, 256>>>(erow);                        // 5
    k_scan1<<<SCAN_NBLK, SCAN_B>>>();
    k_scan2<<<1, 1>>>();
    k_scan3<<<(NN + 255) / 256, 256>>>();
    k_fill<<<(EE + 255) / 256, 256>>>(erow, ecol, ew);

    for (int s = 0; s < 3; s++) {
        k_spmm<<<((NN / 2) * 32 + 255) / 256, 256>>>();
        dim3 gg(NGBLK, 2);
        k_gates1<<<gg, 256, SMEM_DYN>>>(ugb, rgb);
        k_gates2<<<NGBLK, 256, SMEM_DYN>>>((s == 2) ? out : (float*)nullptr);
    }
}